// round 1
// baseline (speedup 1.0000x reference)
#include <cuda_runtime.h>
#include <math.h>

#define DIM 1024
#define BSZ 4
#define SEQ 1024
#define NH 16
#define HD 64
#define MTOT (BSZ*SEQ)

// Scratch (zero-init bss, no allocations)
__device__ float g_q[MTOT*DIM];
__device__ float g_k[MTOT*DIM];
__device__ float g_v[MTOT*DIM];
__device__ float g_att[MTOT*DIM];

// ---------------------------------------------------------------------------
// SGEMM: C[m,n] = sum_k A[m,k] * W[n,k] (+ bias[n])   (both row-major, NT)
// BM=BN=128, BK=16, 256 threads, 8x8 microtile (split 4+4 across halves)
// ---------------------------------------------------------------------------
#define BM 128
#define BN 128
#define BK 16

template<bool BIAS>
__global__ void __launch_bounds__(256) sgemm_nt(const float* __restrict__ A,
                                                const float* __restrict__ W,
                                                const float* __restrict__ bias,
                                                float* __restrict__ C,
                                                int M, int N, int K)
{
    __shared__ float As[BK][BM];   // transposed: As[k][m]
    __shared__ float Bs[BK][BN];   // transposed: Bs[k][n]

    int tid = threadIdx.x;
    int tx = tid & 15;
    int ty = tid >> 4;
    int m0 = blockIdx.y * BM;
    int n0 = blockIdx.x * BN;

    float acc[8][8];
#pragma unroll
    for (int i = 0; i < 8; i++)
#pragma unroll
        for (int j = 0; j < 8; j++) acc[i][j] = 0.0f;

    for (int k0 = 0; k0 < K; k0 += BK) {
        // Load tiles: 128 rows x 16 k = 512 float4 per matrix, 2 per thread
#pragma unroll
        for (int r = 0; r < 2; r++) {
            int f = tid + 256 * r;      // 0..511
            int row = f >> 2;
            int kq = f & 3;
            float4 va = *(const float4*)&A[(size_t)(m0 + row) * K + k0 + kq * 4];
            As[kq*4+0][row] = va.x; As[kq*4+1][row] = va.y;
            As[kq*4+2][row] = va.z; As[kq*4+3][row] = va.w;
            float4 vb = *(const float4*)&W[(size_t)(n0 + row) * K + k0 + kq * 4];
            Bs[kq*4+0][row] = vb.x; Bs[kq*4+1][row] = vb.y;
            Bs[kq*4+2][row] = vb.z; Bs[kq*4+3][row] = vb.w;
        }
        __syncthreads();

#pragma unroll
        for (int k = 0; k < BK; k++) {
            float a[8], b[8];
            *(float4*)&a[0] = *(const float4*)&As[k][ty * 4];
            *(float4*)&a[4] = *(const float4*)&As[k][64 + ty * 4];
            *(float4*)&b[0] = *(const float4*)&Bs[k][tx * 4];
            *(float4*)&b[4] = *(const float4*)&Bs[k][64 + tx * 4];
#pragma unroll
            for (int i = 0; i < 8; i++)
#pragma unroll
                for (int j = 0; j < 8; j++)
                    acc[i][j] += a[i] * b[j];
        }
        __syncthreads();
    }

    // Writeback (2x2 blocks of 4x4)
#pragma unroll
    for (int ih = 0; ih < 2; ih++) {
#pragma unroll
        for (int i = 0; i < 4; i++) {
            int row = m0 + ih * 64 + ty * 4 + i;
#pragma unroll
            for (int jh = 0; jh < 2; jh++) {
                int col = n0 + jh * 64 + tx * 4;
                float4 o;
                o.x = acc[ih*4+i][jh*4+0];
                o.y = acc[ih*4+i][jh*4+1];
                o.z = acc[ih*4+i][jh*4+2];
                o.w = acc[ih*4+i][jh*4+3];
                if (BIAS) {
                    o.x += bias[col+0]; o.y += bias[col+1];
                    o.z += bias[col+2]; o.w += bias[col+3];
                }
                *(float4*)&C[(size_t)row * N + col] = o;
            }
        }
    }
}

// ---------------------------------------------------------------------------
// RoPE over full DIM for q and k (positions = s, start_pos = 0)
// ---------------------------------------------------------------------------
__global__ void rope_kernel(float* __restrict__ q, float* __restrict__ k)
{
    const int HALF = DIM / 2;
    int idx = blockIdx.x * blockDim.x + threadIdx.x;
    if (idx >= MTOT * HALF) return;
    int p = idx % HALF;                // pair index i -> dims 2i, 2i+1
    int row = idx / HALF;
    int s = row % SEQ;

    float ex = (float)(2 * p) / (float)DIM;
    float freq = powf(10000.0f, -ex);
    float ang = (float)s * freq;
    float sn, cs;
    sincosf(ang, &sn, &cs);

    size_t base = (size_t)row * DIM + 2 * p;
    float q0 = q[base], q1 = q[base + 1];
    q[base]     = q0 * cs - q1 * sn;
    q[base + 1] = q0 * sn + q1 * cs;
    float k0 = k[base], k1 = k[base + 1];
    k[base]     = k0 * cs - k1 * sn;
    k[base + 1] = k0 * sn + k1 * cs;
}

// ---------------------------------------------------------------------------
// Flash attention, fp32, 64 q-rows per CTA, streams over 16 k-tiles of 64.
// Thread layout 16x16, each thread owns 4 q-rows x 4 cols.
// Shared (dynamic, 52224 B): qs_t[d][q], ks_t[d][k] (reused as ps[q][k]), vs[k][d]
// all stride 68 floats (16B-aligned rows, good bank spread).
// ---------------------------------------------------------------------------
#define FS 68
#define FLASH_SMEM (3 * 64 * FS * 4)

__global__ void __launch_bounds__(256) flash_kernel(const float* __restrict__ Q,
                                                    const float* __restrict__ Km,
                                                    const float* __restrict__ V,
                                                    float* __restrict__ O)
{
    extern __shared__ float sm[];
    float* qs = sm;                // [64][FS] transposed: qs[d*FS + q]
    float* ks = sm + 64 * FS;      // [64][FS] transposed: ks[d*FS + k]; reused as ps[q*FS + k]
    float* vs = sm + 2 * 64 * FS;  // [64][FS] row-major: vs[k*FS + d]

    int tid = threadIdx.x;
    int tx = tid & 15;
    int ty = tid >> 4;
    int b = blockIdx.z, h = blockIdx.y;
    int q0 = blockIdx.x * 64;

    const float* Qb = Q  + ((size_t)(b * SEQ + q0)) * DIM + h * HD;
    const float* Kb = Km + ((size_t)(b * SEQ)) * DIM + h * HD;
    const float* Vb = V  + ((size_t)(b * SEQ)) * DIM + h * HD;

    // Load Q tile transposed: 64 rows x 64 d
#pragma unroll
    for (int r = 0; r < 4; r++) {
        int f = tid + 256 * r;      // 0..1023
        int row = f >> 4;
        int dq = f & 15;
        float4 v = *(const float4*)&Qb[(size_t)row * DIM + dq * 4];
        qs[(dq*4+0)*FS + row] = v.x; qs[(dq*4+1)*FS + row] = v.y;
        qs[(dq*4+2)*FS + row] = v.z; qs[(dq*4+3)*FS + row] = v.w;
    }

    float o[4][4];
    float mrow[4], lrow[4];
#pragma unroll
    for (int i = 0; i < 4; i++) {
        mrow[i] = -INFINITY; lrow[i] = 0.0f;
#pragma unroll
        for (int j = 0; j < 4; j++) o[i][j] = 0.0f;
    }

    const float SCALE = 0.125f;   // 1/sqrt(64)

    for (int kt = 0; kt < SEQ / 64; kt++) {
        const float* Kt = Kb + (size_t)kt * 64 * DIM;
        const float* Vt = Vb + (size_t)kt * 64 * DIM;
        __syncthreads();   // previous iteration's pv-loop done before overwrite
        // Load K tile transposed + V tile row-major
#pragma unroll
        for (int r = 0; r < 4; r++) {
            int f = tid + 256 * r;
            int row = f >> 4;
            int dq = f & 15;
            float4 kv4 = *(const float4*)&Kt[(size_t)row * DIM + dq * 4];
            ks[(dq*4+0)*FS + row] = kv4.x; ks[(dq*4+1)*FS + row] = kv4.y;
            ks[(dq*4+2)*FS + row] = kv4.z; ks[(dq*4+3)*FS + row] = kv4.w;
            float4 vv4 = *(const float4*)&Vt[(size_t)row * DIM + dq * 4];
            *(float4*)&vs[row * FS + dq * 4] = vv4;
        }
        __syncthreads();

        // s[i][j] = sum_d q[ty*4+i][d] * k[tx*4+j][d]
        float s[4][4];
#pragma unroll
        for (int i = 0; i < 4; i++)
#pragma unroll
            for (int j = 0; j < 4; j++) s[i][j] = 0.0f;

#pragma unroll 8
        for (int d = 0; d < 64; d++) {
            float4 qv = *(const float4*)&qs[d * FS + ty * 4];
            float4 kv = *(const float4*)&ks[d * FS + tx * 4];
            float qa[4] = {qv.x, qv.y, qv.z, qv.w};
            float ka[4] = {kv.x, kv.y, kv.z, kv.w};
#pragma unroll
            for (int i = 0; i < 4; i++)
#pragma unroll
                for (int j = 0; j < 4; j++)
                    s[i][j] += qa[i] * ka[j];
        }

        // Online softmax update (row groups of 16 lanes share a q-row set)
        float p[4][4];
        float scale_i[4];
#pragma unroll
        for (int i = 0; i < 4; i++) {
            float tm = s[i][0] * SCALE;
#pragma unroll
            for (int j = 1; j < 4; j++) tm = fmaxf(tm, s[i][j] * SCALE);
#pragma unroll
            for (int msk = 8; msk >= 1; msk >>= 1)
                tm = fmaxf(tm, __shfl_xor_sync(0xffffffffu, tm, msk));
            float mn = fmaxf(mrow[i], tm);
            scale_i[i] = expf(mrow[i] - mn);
            float rs = 0.0f;
#pragma unroll
            for (int j = 0; j < 4; j++) {
                p[i][j] = expf(s[i][j] * SCALE - mn);
                rs += p[i][j];
            }
#pragma unroll
            for (int msk = 8; msk >= 1; msk >>= 1)
                rs += __shfl_xor_sync(0xffffffffu, rs, msk);
            lrow[i] = lrow[i] * scale_i[i] + rs;
            mrow[i] = mn;
#pragma unroll
            for (int j = 0; j < 4; j++) o[i][j] *= scale_i[i];
        }

        __syncthreads();   // everyone done reading ks before reuse as ps
#pragma unroll
        for (int i = 0; i < 4; i++)
#pragma unroll
            for (int j = 0; j < 4; j++)
                ks[(ty * 4 + i) * FS + tx * 4 + j] = p[i][j];
        __syncthreads();

        // o[i][j] += sum_k p[q][k] * v[k][d]
#pragma unroll 8
        for (int k = 0; k < 64; k++) {
            float4 vv = *(const float4*)&vs[k * FS + tx * 4];
            float va[4] = {vv.x, vv.y, vv.z, vv.w};
            float pv[4];
#pragma unroll
            for (int i = 0; i < 4; i++) pv[i] = ks[(ty * 4 + i) * FS + k];
#pragma unroll
            for (int i = 0; i < 4; i++)
#pragma unroll
                for (int j = 0; j < 4; j++)
                    o[i][j] += pv[i] * va[j];
        }
    }

    // Write normalized output into [B,S,DIM] layout at head's columns
#pragma unroll
    for (int i = 0; i < 4; i++) {
        float inv = 1.0f / lrow[i];
        float4 ov;
        ov.x = o[i][0] * inv; ov.y = o[i][1] * inv;
        ov.z = o[i][2] * inv; ov.w = o[i][3] * inv;
        size_t row = (size_t)(b * SEQ + q0 + ty * 4 + i);
        *(float4*)&O[row * DIM + h * HD + tx * 4] = ov;
    }
}

// ---------------------------------------------------------------------------
// Launch
// ---------------------------------------------------------------------------
extern "C" void kernel_launch(void* const* d_in, const int* in_sizes, int n_in,
                              void* d_out, int out_size)
{
    const float* x  = (const float*)d_in[0];
    const float* Wq = (const float*)d_in[1];
    const float* Wk = (const float*)d_in[2];
    const float* Wv = (const float*)d_in[3];
    const float* Wo = (const float*)d_in[4];
    const float* bo = (const float*)d_in[5];
    float* out = (float*)d_out;

    float *gq, *gk, *gv, *ga;
    cudaGetSymbolAddress((void**)&gq, g_q);
    cudaGetSymbolAddress((void**)&gk, g_k);
    cudaGetSymbolAddress((void**)&gv, g_v);
    cudaGetSymbolAddress((void**)&ga, g_att);

    cudaFuncSetAttribute(flash_kernel,
                         cudaFuncAttributeMaxDynamicSharedMemorySize, FLASH_SMEM);

    dim3 gg(DIM / BN, MTOT / BM);   // (8, 32)

    sgemm_nt<false><<<gg, 256>>>(x, Wq, nullptr, gq, MTOT, DIM, DIM);
    sgemm_nt<false><<<gg, 256>>>(x, Wk, nullptr, gk, MTOT, DIM, DIM);
    sgemm_nt<false><<<gg, 256>>>(x, Wv, nullptr, gv, MTOT, DIM, DIM);

    int pairs = MTOT * (DIM / 2);
    rope_kernel<<<(pairs + 255) / 256, 256>>>(gq, gk);

    flash_kernel<<<dim3(SEQ / 64, NH, BSZ), 256, FLASH_SMEM>>>(gq, gk, gv, ga);

    sgemm_nt<true><<<gg, 256>>>(ga, Wo, bo, out, MTOT, DIM, DIM);
}

// round 3
// speedup vs baseline: 1.5823x; 1.5823x over previous
#include <cuda_runtime.h>
#include <cuda_bf16.h>
#include <math.h>
#include <stdint.h>

#define DIM 1024
#define BSZ 4
#define SEQ 1024
#define NH 16
#define HD 64
#define MTOT (BSZ*SEQ)

// ---------------------------------------------------------------------------
// Scratch (device globals, no allocations)
// ---------------------------------------------------------------------------
__device__ float g_q[MTOT*DIM];
__device__ float g_k[MTOT*DIM];
__device__ float g_v[MTOT*DIM];
__device__ unsigned short g_xh[MTOT*DIM], g_xl[MTOT*DIM];   // x split
__device__ unsigned short g_ah[MTOT*DIM], g_al[MTOT*DIM];   // attn-out split
__device__ unsigned short g_wqh[DIM*DIM], g_wql[DIM*DIM];
__device__ unsigned short g_wkh[DIM*DIM], g_wkl[DIM*DIM];
__device__ unsigned short g_wvh[DIM*DIM], g_wvl[DIM*DIM];
__device__ unsigned short g_woh[DIM*DIM], g_wol[DIM*DIM];

// ---------------------------------------------------------------------------
// Helpers (base-target PTX only: ldmatrix / mma.sync / cp.async)
// ---------------------------------------------------------------------------
__device__ __forceinline__ uint32_t smem_u32(const void* p) {
    uint32_t a;
    asm("{ .reg .u64 t; cvta.to.shared.u64 t, %1; cvt.u32.u64 %0, t; }" : "=r"(a) : "l"(p));
    return a;
}

__device__ __forceinline__ void ldsm4(uint32_t* r, uint32_t addr) {
    asm volatile("ldmatrix.sync.aligned.m8n8.x4.shared.b16 {%0,%1,%2,%3}, [%4];"
                 : "=r"(r[0]), "=r"(r[1]), "=r"(r[2]), "=r"(r[3]) : "r"(addr));
}

__device__ __forceinline__ void mma16816(float* c, const uint32_t* a, const uint32_t* b) {
    asm volatile(
        "mma.sync.aligned.m16n8k16.row.col.f32.bf16.bf16.f32 "
        "{%0,%1,%2,%3}, {%4,%5,%6,%7}, {%8,%9}, {%0,%1,%2,%3};\n"
        : "+f"(c[0]), "+f"(c[1]), "+f"(c[2]), "+f"(c[3])
        : "r"(a[0]), "r"(a[1]), "r"(a[2]), "r"(a[3]), "r"(b[0]), "r"(b[1]));
}

__device__ __forceinline__ void cp16(uint32_t saddr, const void* g) {
    asm volatile("cp.async.cg.shared.global [%0], [%1], 16;" :: "r"(saddr), "l"(g));
}
#define CP_COMMIT() asm volatile("cp.async.commit_group;" ::: "memory")
#define CP_WAIT(n)  asm volatile("cp.async.wait_group %0;" :: "n"(n) : "memory")

// ---------------------------------------------------------------------------
// fp32 -> (bf16 hi, bf16 lo) split.  hi = truncate-to-bf16, lo = rn(residual)
// ---------------------------------------------------------------------------
__global__ void split_kernel(const float* __restrict__ src,
                             unsigned short* __restrict__ hi,
                             unsigned short* __restrict__ lo, int n4)
{
    int i = blockIdx.x * blockDim.x + threadIdx.x;
    if (i >= n4) return;
    float4 v = ((const float4*)src)[i];
    float vv[4] = {v.x, v.y, v.z, v.w};
    unsigned short h[4], l[4];
#pragma unroll
    for (int j = 0; j < 4; j++) {
        uint32_t b  = __float_as_uint(vv[j]);
        uint32_t hb = b & 0xFFFF0000u;
        h[j] = (unsigned short)(hb >> 16);
        l[j] = __bfloat16_as_ushort(__float2bfloat16(vv[j] - __uint_as_float(hb)));
    }
    ((uint2*)hi)[i] = make_uint2((uint32_t)h[0] | ((uint32_t)h[1] << 16),
                                 (uint32_t)h[2] | ((uint32_t)h[3] << 16));
    ((uint2*)lo)[i] = make_uint2((uint32_t)l[0] | ((uint32_t)l[1] << 16),
                                 (uint32_t)l[2] | ((uint32_t)l[3] << 16));
}

// ---------------------------------------------------------------------------
// HMMA GEMM:  C[m,n] = sum_k A[m,k]*B[n,k] (+bias), bf16-split, 3-pass comp.
// CTA tile 128x128, BK=32, 8 warps (2x4), warp tile 64x32.
// Smem: padded stride 56 elems (112B) -> 16B-aligned rows, conflict-free LDSM.
// ---------------------------------------------------------------------------
#define GBM 128
#define GBN 128
#define GBK 32
#define GST 56                     // smem row stride (bf16 elems)
#define GBUF (128*GST*2)           // 14336 B per matrix buffer
#define GSTG (4*GBUF)              // Ah,Al,Bh,Bl per stage
#define GEMM_SMEM (2*GSTG)         // 114688 B
#define GNKB (DIM/GBK)             // 32

template<bool BIAS>
__global__ void __launch_bounds__(256, 1)
gemm_hmma(const unsigned short* __restrict__ Ah,
          const unsigned short* __restrict__ Al,
          const unsigned short* __restrict__ Bh,
          const unsigned short* __restrict__ Bl,
          const float* __restrict__ bias,
          float* __restrict__ C)
{
    extern __shared__ char smc[];
    uint32_t sbase = smem_u32(smc);
    int tid  = threadIdx.x;
    int wid  = tid >> 5, lane = tid & 31;
    int wm   = wid >> 2;           // 0..1
    int wn   = wid & 3;            // 0..3
    int m0   = blockIdx.y * GBM;
    int n0   = blockIdx.x * GBN;

    const unsigned short* gA[2] = { Ah + (size_t)m0 * DIM, Al + (size_t)m0 * DIM };
    const unsigned short* gB[2] = { Bh + (size_t)n0 * DIM, Bl + (size_t)n0 * DIM };

    // per-thread load coords: 2 chunks of 16B per matrix per stage
    int c0row[2], c0kc[2];
#pragma unroll
    for (int r = 0; r < 2; r++) { int c = tid + 256 * r; c0row[r] = c >> 2; c0kc[r] = c & 3; }

    auto load_stage = [&](int p, int kb) {
        uint32_t sb = sbase + p * GSTG;
#pragma unroll
        for (int r = 0; r < 2; r++) {
            int row = c0row[r], kc = c0kc[r];
            uint32_t so = (uint32_t)(row * GST + kc * 8) * 2;
            size_t go = (size_t)row * DIM + kb * GBK + kc * 8;
            cp16(sb + 0 * GBUF + so, gA[0] + go);
            cp16(sb + 1 * GBUF + so, gA[1] + go);
            cp16(sb + 2 * GBUF + so, gB[0] + go);
            cp16(sb + 3 * GBUF + so, gB[1] + go);
        }
    };

    float acc[4][4][4];
#pragma unroll
    for (int i = 0; i < 4; i++)
#pragma unroll
        for (int j = 0; j < 4; j++)
#pragma unroll
            for (int q = 0; q < 4; q++) acc[i][j][q] = 0.0f;

    // A frag addr pieces (row fixed per mt, chunk varies with ks)
    int a_row_lane = lane & 15;
    int a_hi8      = lane >> 4;           // 0/1 -> k chunk +0/+1
    int b_row_lane = (lane & 7) + ((lane & 16) ? 8 : 0);
    int b_hi8      = (lane >> 3) & 1;

    load_stage(0, 0); CP_COMMIT();

    for (int kb = 0; kb < GNKB; kb++) {
        if (kb + 1 < GNKB) { load_stage((kb + 1) & 1, kb + 1); CP_COMMIT(); CP_WAIT(1); }
        else CP_WAIT(0);
        __syncthreads();

        uint32_t sb  = sbase + (kb & 1) * GSTG;
        uint32_t sAh = sb, sAl = sb + GBUF, sBh = sb + 2 * GBUF, sBl = sb + 3 * GBUF;

#pragma unroll
        for (int ks = 0; ks < 2; ks++) {
            uint32_t aH[4][4], aL[4][4], bH[4][2], bL[4][2];
#pragma unroll
            for (int mt = 0; mt < 4; mt++) {
                int row = wm * 64 + mt * 16 + a_row_lane;
                int ch  = ks * 2 + a_hi8;
                uint32_t off = (uint32_t)(row * GST + ch * 8) * 2;
                ldsm4(aH[mt], sAh + off);
                ldsm4(aL[mt], sAl + off);
            }
#pragma unroll
            for (int nt2 = 0; nt2 < 2; nt2++) {
                int row = wn * 32 + nt2 * 16 + b_row_lane;
                int ch  = ks * 2 + b_hi8;
                uint32_t off = (uint32_t)(row * GST + ch * 8) * 2;
                uint32_t r4[4];
                ldsm4(r4, sBh + off);
                bH[nt2*2][0] = r4[0]; bH[nt2*2][1] = r4[1];
                bH[nt2*2+1][0] = r4[2]; bH[nt2*2+1][1] = r4[3];
                ldsm4(r4, sBl + off);
                bL[nt2*2][0] = r4[0]; bL[nt2*2][1] = r4[1];
                bL[nt2*2+1][0] = r4[2]; bL[nt2*2+1][1] = r4[3];
            }
#pragma unroll
            for (int mt = 0; mt < 4; mt++)
#pragma unroll
                for (int nt = 0; nt < 4; nt++)
                    mma16816(acc[mt][nt], aH[mt], bH[nt]);
#pragma unroll
            for (int mt = 0; mt < 4; mt++)
#pragma unroll
                for (int nt = 0; nt < 4; nt++)
                    mma16816(acc[mt][nt], aH[mt], bL[nt]);
#pragma unroll
            for (int mt = 0; mt < 4; mt++)
#pragma unroll
                for (int nt = 0; nt < 4; nt++)
                    mma16816(acc[mt][nt], aL[mt], bH[nt]);
        }
        __syncthreads();
    }

    // Epilogue
#pragma unroll
    for (int mt = 0; mt < 4; mt++) {
        int row = m0 + wm * 64 + mt * 16 + (lane >> 2);
#pragma unroll
        for (int nt = 0; nt < 4; nt++) {
            int col = n0 + wn * 32 + nt * 8 + (lane & 3) * 2;
            float2 v0 = make_float2(acc[mt][nt][0], acc[mt][nt][1]);
            float2 v1 = make_float2(acc[mt][nt][2], acc[mt][nt][3]);
            if (BIAS) {
                v0.x += bias[col]; v0.y += bias[col + 1];
                v1.x += bias[col]; v1.y += bias[col + 1];
            }
            *(float2*)&C[(size_t)row * DIM + col] = v0;
            *(float2*)&C[(size_t)(row + 8) * DIM + col] = v1;
        }
    }
}

// ---------------------------------------------------------------------------
// RoPE over full DIM for q and k
// ---------------------------------------------------------------------------
__global__ void rope_kernel(float* __restrict__ q, float* __restrict__ k)
{
    const int HALF = DIM / 2;
    int idx = blockIdx.x * blockDim.x + threadIdx.x;
    if (idx >= MTOT * HALF) return;
    int p = idx % HALF;
    int row = idx / HALF;
    int s = row % SEQ;

    float ex = (float)(2 * p) / (float)DIM;
    float freq = powf(10000.0f, -ex);
    float ang = (float)s * freq;
    float sn, cs;
    sincosf(ang, &sn, &cs);

    size_t base = (size_t)row * DIM + 2 * p;
    float q0 = q[base], q1 = q[base + 1];
    q[base]     = q0 * cs - q1 * sn;
    q[base + 1] = q0 * sn + q1 * cs;
    float k0 = k[base], k1 = k[base + 1];
    k[base]     = k0 * cs - k1 * sn;
    k[base + 1] = k0 * sn + k1 * cs;
}

// ---------------------------------------------------------------------------
// Flash attention (fp32), epilogue writes bf16-split output for the O-proj.
// ---------------------------------------------------------------------------
#define FS 68
#define FLASH_SMEM (3 * 64 * FS * 4)

__global__ void __launch_bounds__(256) flash_kernel(const float* __restrict__ Q,
                                                    const float* __restrict__ Km,
                                                    const float* __restrict__ V,
                                                    unsigned short* __restrict__ Oh,
                                                    unsigned short* __restrict__ Ol)
{
    extern __shared__ float smf[];
    float* qs = smf;
    float* ks = smf + 64 * FS;
    float* vs = smf + 2 * 64 * FS;

    int tid = threadIdx.x;
    int tx = tid & 15;
    int ty = tid >> 4;
    int b = blockIdx.z, h = blockIdx.y;
    int q0 = blockIdx.x * 64;

    const float* Qb = Q  + ((size_t)(b * SEQ + q0)) * DIM + h * HD;
    const float* Kb = Km + ((size_t)(b * SEQ)) * DIM + h * HD;
    const float* Vb = V  + ((size_t)(b * SEQ)) * DIM + h * HD;

#pragma unroll
    for (int r = 0; r < 4; r++) {
        int f = tid + 256 * r;
        int row = f >> 4;
        int dq = f & 15;
        float4 v = *(const float4*)&Qb[(size_t)row * DIM + dq * 4];
        qs[(dq*4+0)*FS + row] = v.x; qs[(dq*4+1)*FS + row] = v.y;
        qs[(dq*4+2)*FS + row] = v.z; qs[(dq*4+3)*FS + row] = v.w;
    }

    float o[4][4];
    float mrow[4], lrow[4];
#pragma unroll
    for (int i = 0; i < 4; i++) {
        mrow[i] = -INFINITY; lrow[i] = 0.0f;
#pragma unroll
        for (int j = 0; j < 4; j++) o[i][j] = 0.0f;
    }

    const float SCALE = 0.125f;

    for (int kt = 0; kt < SEQ / 64; kt++) {
        const float* Kt = Kb + (size_t)kt * 64 * DIM;
        const float* Vt = Vb + (size_t)kt * 64 * DIM;
        __syncthreads();
#pragma unroll
        for (int r = 0; r < 4; r++) {
            int f = tid + 256 * r;
            int row = f >> 4;
            int dq = f & 15;
            float4 kv4 = *(const float4*)&Kt[(size_t)row * DIM + dq * 4];
            ks[(dq*4+0)*FS + row] = kv4.x; ks[(dq*4+1)*FS + row] = kv4.y;
            ks[(dq*4+2)*FS + row] = kv4.z; ks[(dq*4+3)*FS + row] = kv4.w;
            float4 vv4 = *(const float4*)&Vt[(size_t)row * DIM + dq * 4];
            *(float4*)&vs[row * FS + dq * 4] = vv4;
        }
        __syncthreads();

        float s[4][4];
#pragma unroll
        for (int i = 0; i < 4; i++)
#pragma unroll
            for (int j = 0; j < 4; j++) s[i][j] = 0.0f;

#pragma unroll 8
        for (int d = 0; d < 64; d++) {
            float4 qv = *(const float4*)&qs[d * FS + ty * 4];
            float4 kv = *(const float4*)&ks[d * FS + tx * 4];
            float qa[4] = {qv.x, qv.y, qv.z, qv.w};
            float ka[4] = {kv.x, kv.y, kv.z, kv.w};
#pragma unroll
            for (int i = 0; i < 4; i++)
#pragma unroll
                for (int j = 0; j < 4; j++)
                    s[i][j] += qa[i] * ka[j];
        }

        float p[4][4];
        float scale_i[4];
#pragma unroll
        for (int i = 0; i < 4; i++) {
            float tm = s[i][0] * SCALE;
#pragma unroll
            for (int j = 1; j < 4; j++) tm = fmaxf(tm, s[i][j] * SCALE);
#pragma unroll
            for (int msk = 8; msk >= 1; msk >>= 1)
                tm = fmaxf(tm, __shfl_xor_sync(0xffffffffu, tm, msk));
            float mn = fmaxf(mrow[i], tm);
            scale_i[i] = expf(mrow[i] - mn);
            float rs = 0.0f;
#pragma unroll
            for (int j = 0; j < 4; j++) {
                p[i][j] = expf(s[i][j] * SCALE - mn);
                rs += p[i][j];
            }
#pragma unroll
            for (int msk = 8; msk >= 1; msk >>= 1)
                rs += __shfl_xor_sync(0xffffffffu, rs, msk);
            lrow[i] = lrow[i] * scale_i[i] + rs;
            mrow[i] = mn;
#pragma unroll
            for (int j = 0; j < 4; j++) o[i][j] *= scale_i[i];
        }

        __syncthreads();
#pragma unroll
        for (int i = 0; i < 4; i++)
#pragma unroll
            for (int j = 0; j < 4; j++)
                ks[(ty * 4 + i) * FS + tx * 4 + j] = p[i][j];
        __syncthreads();

#pragma unroll 8
        for (int k = 0; k < 64; k++) {
            float4 vv = *(const float4*)&vs[k * FS + tx * 4];
            float va[4] = {vv.x, vv.y, vv.z, vv.w};
            float pv[4];
#pragma unroll
            for (int i = 0; i < 4; i++) pv[i] = ks[(ty * 4 + i) * FS + k];
#pragma unroll
            for (int i = 0; i < 4; i++)
#pragma unroll
                for (int j = 0; j < 4; j++)
                    o[i][j] += pv[i] * va[j];
        }
    }

    // Epilogue: normalize + bf16 hi/lo split, write to [B,S,DIM] layout
#pragma unroll
    for (int i = 0; i < 4; i++) {
        float inv = 1.0f / lrow[i];
        unsigned short hs[4], ls[4];
#pragma unroll
        for (int j = 0; j < 4; j++) {
            float f = o[i][j] * inv;
            uint32_t bb = __float_as_uint(f);
            uint32_t hb = bb & 0xFFFF0000u;
            hs[j] = (unsigned short)(hb >> 16);
            ls[j] = __bfloat16_as_ushort(__float2bfloat16(f - __uint_as_float(hb)));
        }
        size_t base = (size_t)(b * SEQ + q0 + ty * 4 + i) * DIM + h * HD + tx * 4;
        *(uint2*)&Oh[base] = make_uint2((uint32_t)hs[0] | ((uint32_t)hs[1] << 16),
                                        (uint32_t)hs[2] | ((uint32_t)hs[3] << 16));
        *(uint2*)&Ol[base] = make_uint2((uint32_t)ls[0] | ((uint32_t)ls[1] << 16),
                                        (uint32_t)ls[2] | ((uint32_t)ls[3] << 16));
    }
}

// ---------------------------------------------------------------------------
// Launch
// ---------------------------------------------------------------------------
extern "C" void kernel_launch(void* const* d_in, const int* in_sizes, int n_in,
                              void* d_out, int out_size)
{
    const float* x  = (const float*)d_in[0];
    const float* Wq = (const float*)d_in[1];
    const float* Wk = (const float*)d_in[2];
    const float* Wv = (const float*)d_in[3];
    const float* Wo = (const float*)d_in[4];
    const float* bo = (const float*)d_in[5];
    float* out = (float*)d_out;

    float *gq, *gk, *gv;
    unsigned short *xh, *xl, *ah, *al;
    unsigned short *wqh, *wql, *wkh, *wkl, *wvh, *wvl, *woh, *wol;
    cudaGetSymbolAddress((void**)&gq, g_q);
    cudaGetSymbolAddress((void**)&gk, g_k);
    cudaGetSymbolAddress((void**)&gv, g_v);
    cudaGetSymbolAddress((void**)&xh, g_xh);
    cudaGetSymbolAddress((void**)&xl, g_xl);
    cudaGetSymbolAddress((void**)&ah, g_ah);
    cudaGetSymbolAddress((void**)&al, g_al);
    cudaGetSymbolAddress((void**)&wqh, g_wqh);
    cudaGetSymbolAddress((void**)&wql, g_wql);
    cudaGetSymbolAddress((void**)&wkh, g_wkh);
    cudaGetSymbolAddress((void**)&wkl, g_wkl);
    cudaGetSymbolAddress((void**)&wvh, g_wvh);
    cudaGetSymbolAddress((void**)&wvl, g_wvl);
    cudaGetSymbolAddress((void**)&woh, g_woh);
    cudaGetSymbolAddress((void**)&wol, g_wol);

    cudaFuncSetAttribute(gemm_hmma<false>,
                         cudaFuncAttributeMaxDynamicSharedMemorySize, GEMM_SMEM);
    cudaFuncSetAttribute(gemm_hmma<true>,
                         cudaFuncAttributeMaxDynamicSharedMemorySize, GEMM_SMEM);
    cudaFuncSetAttribute(flash_kernel,
                         cudaFuncAttributeMaxDynamicSharedMemorySize, FLASH_SMEM);

    // Split fp32 -> bf16 hi/lo
    int n4x = MTOT * DIM / 4;
    int n4w = DIM * DIM / 4;
    split_kernel<<<(n4x + 255) / 256, 256>>>(x, xh, xl, n4x);
    split_kernel<<<(n4w + 255) / 256, 256>>>(Wq, wqh, wql, n4w);
    split_kernel<<<(n4w + 255) / 256, 256>>>(Wk, wkh, wkl, n4w);
    split_kernel<<<(n4w + 255) / 256, 256>>>(Wv, wvh, wvl, n4w);
    split_kernel<<<(n4w + 255) / 256, 256>>>(Wo, woh, wol, n4w);

    dim3 gg(DIM / GBN, MTOT / GBM);   // (8, 32)
    gemm_hmma<false><<<gg, 256, GEMM_SMEM>>>(xh, xl, wqh, wql, nullptr, gq);
    gemm_hmma<false><<<gg, 256, GEMM_SMEM>>>(xh, xl, wkh, wkl, nullptr, gk);
    gemm_hmma<false><<<gg, 256, GEMM_SMEM>>>(xh, xl, wvh, wvl, nullptr, gv);

    int pairs = MTOT * (DIM / 2);
    rope_kernel<<<(pairs + 255) / 256, 256>>>(gq, gk);

    flash_kernel<<<dim3(SEQ / 64, NH, BSZ), 256, FLASH_SMEM>>>(gq, gk, gv, ah, al);

    gemm_hmma<true><<<gg, 256, GEMM_SMEM>>>(ah, al, woh, wol, bo, out);
}

// round 5
// speedup vs baseline: 2.5303x; 1.5991x over previous
#include <cuda_runtime.h>
#include <cuda_bf16.h>
#include <math.h>
#include <stdint.h>

#define DIM 1024
#define BSZ 4
#define SEQ 1024
#define NH 16
#define HD 64
#define MTOT (BSZ*SEQ)

// ---------------------------------------------------------------------------
// Scratch (device globals, no allocations)
// ---------------------------------------------------------------------------
__device__ float g_q[MTOT*DIM];
__device__ float g_k[MTOT*DIM];
__device__ unsigned short g_xh[MTOT*DIM], g_xl[MTOT*DIM];
__device__ unsigned short g_qh[MTOT*DIM], g_ql[MTOT*DIM];
__device__ unsigned short g_kh[MTOT*DIM], g_kl[MTOT*DIM];
__device__ unsigned short g_vh[MTOT*DIM], g_vl[MTOT*DIM];
__device__ unsigned short g_ah[MTOT*DIM], g_al[MTOT*DIM];
__device__ unsigned short g_wqh[DIM*DIM], g_wql[DIM*DIM];
__device__ unsigned short g_wkh[DIM*DIM], g_wkl[DIM*DIM];
__device__ unsigned short g_wvh[DIM*DIM], g_wvl[DIM*DIM];
__device__ unsigned short g_woh[DIM*DIM], g_wol[DIM*DIM];

// ---------------------------------------------------------------------------
// Helpers (base-target PTX only)
// ---------------------------------------------------------------------------
__device__ __forceinline__ uint32_t smem_u32(const void* p) {
    uint32_t a;
    asm("{ .reg .u64 t; cvta.to.shared.u64 t, %1; cvt.u32.u64 %0, t; }" : "=r"(a) : "l"(p));
    return a;
}

__device__ __forceinline__ void ldsm4(uint32_t* r, uint32_t addr) {
    asm volatile("ldmatrix.sync.aligned.m8n8.x4.shared.b16 {%0,%1,%2,%3}, [%4];"
                 : "=r"(r[0]), "=r"(r[1]), "=r"(r[2]), "=r"(r[3]) : "r"(addr));
}
__device__ __forceinline__ void ldsm4t(uint32_t* r, uint32_t addr) {
    asm volatile("ldmatrix.sync.aligned.m8n8.x4.trans.shared.b16 {%0,%1,%2,%3}, [%4];"
                 : "=r"(r[0]), "=r"(r[1]), "=r"(r[2]), "=r"(r[3]) : "r"(addr));
}

__device__ __forceinline__ void mma16816(float* c, const uint32_t* a, const uint32_t* b) {
    asm volatile(
        "mma.sync.aligned.m16n8k16.row.col.f32.bf16.bf16.f32 "
        "{%0,%1,%2,%3}, {%4,%5,%6,%7}, {%8,%9}, {%0,%1,%2,%3};\n"
        : "+f"(c[0]), "+f"(c[1]), "+f"(c[2]), "+f"(c[3])
        : "r"(a[0]), "r"(a[1]), "r"(a[2]), "r"(a[3]), "r"(b[0]), "r"(b[1]));
}

__device__ __forceinline__ void cp16(uint32_t saddr, const void* g) {
    asm volatile("cp.async.cg.shared.global [%0], [%1], 16;" :: "r"(saddr), "l"(g));
}
#define CP_COMMIT() asm volatile("cp.async.commit_group;" ::: "memory")
#define CP_WAIT(n)  asm volatile("cp.async.wait_group %0;" :: "n"(n) : "memory")

__device__ __forceinline__ uint32_t pack_trunc(float c0, float c1) {
    return (__float_as_uint(c1) & 0xFFFF0000u) | (__float_as_uint(c0) >> 16);
}
__device__ __forceinline__ uint32_t pack_resid(float c0, float c1) {
    float r0 = c0 - __uint_as_float(__float_as_uint(c0) & 0xFFFF0000u);
    float r1 = c1 - __uint_as_float(__float_as_uint(c1) & 0xFFFF0000u);
    uint32_t b0 = (uint32_t)__bfloat16_as_ushort(__float2bfloat16(r0));
    uint32_t b1 = (uint32_t)__bfloat16_as_ushort(__float2bfloat16(r1));
    return b0 | (b1 << 16);
}

// ---------------------------------------------------------------------------
// fp32 -> (bf16 hi, bf16 lo) split
// ---------------------------------------------------------------------------
__global__ void split_kernel(const float* __restrict__ src,
                             unsigned short* __restrict__ hi,
                             unsigned short* __restrict__ lo, int n4)
{
    int i = blockIdx.x * blockDim.x + threadIdx.x;
    if (i >= n4) return;
    float4 v = ((const float4*)src)[i];
    float vv[4] = {v.x, v.y, v.z, v.w};
    unsigned short h[4], l[4];
#pragma unroll
    for (int j = 0; j < 4; j++) {
        uint32_t b  = __float_as_uint(vv[j]);
        uint32_t hb = b & 0xFFFF0000u;
        h[j] = (unsigned short)(hb >> 16);
        l[j] = __bfloat16_as_ushort(__float2bfloat16(vv[j] - __uint_as_float(hb)));
    }
    ((uint2*)hi)[i] = make_uint2((uint32_t)h[0] | ((uint32_t)h[1] << 16),
                                 (uint32_t)h[2] | ((uint32_t)h[3] << 16));
    ((uint2*)lo)[i] = make_uint2((uint32_t)l[0] | ((uint32_t)l[1] << 16),
                                 (uint32_t)l[2] | ((uint32_t)l[3] << 16));
}

// ---------------------------------------------------------------------------
// HMMA GEMM (as R3), with selectable epilogue: 0=fp32, 1=fp32+bias, 2=bf16split
// ---------------------------------------------------------------------------
#define GBM 128
#define GBN 128
#define GBK 32
#define GST 56
#define GBUF (128*GST*2)
#define GSTG (4*GBUF)
#define GEMM_SMEM (2*GSTG)
#define GNKB (DIM/GBK)

template<int OUTMODE>
__global__ void __launch_bounds__(256, 1)
gemm_hmma(const unsigned short* __restrict__ Ah,
          const unsigned short* __restrict__ Al,
          const unsigned short* __restrict__ Bh,
          const unsigned short* __restrict__ Bl,
          const float* __restrict__ bias,
          float* __restrict__ C,
          unsigned short* __restrict__ Ch,
          unsigned short* __restrict__ Cl)
{
    extern __shared__ char smc[];
    uint32_t sbase = smem_u32(smc);
    int tid  = threadIdx.x;
    int wid  = tid >> 5, lane = tid & 31;
    int wm   = wid >> 2;
    int wn   = wid & 3;
    int m0   = blockIdx.y * GBM;
    int n0   = blockIdx.x * GBN;

    const unsigned short* gA[2] = { Ah + (size_t)m0 * DIM, Al + (size_t)m0 * DIM };
    const unsigned short* gB[2] = { Bh + (size_t)n0 * DIM, Bl + (size_t)n0 * DIM };

    int c0row[2], c0kc[2];
#pragma unroll
    for (int r = 0; r < 2; r++) { int c = tid + 256 * r; c0row[r] = c >> 2; c0kc[r] = c & 3; }

    auto load_stage = [&](int p, int kb) {
        uint32_t sb = sbase + p * GSTG;
#pragma unroll
        for (int r = 0; r < 2; r++) {
            int row = c0row[r], kc = c0kc[r];
            uint32_t so = (uint32_t)(row * GST + kc * 8) * 2;
            size_t go = (size_t)row * DIM + kb * GBK + kc * 8;
            cp16(sb + 0 * GBUF + so, gA[0] + go);
            cp16(sb + 1 * GBUF + so, gA[1] + go);
            cp16(sb + 2 * GBUF + so, gB[0] + go);
            cp16(sb + 3 * GBUF + so, gB[1] + go);
        }
    };

    float acc[4][4][4];
#pragma unroll
    for (int i = 0; i < 4; i++)
#pragma unroll
        for (int j = 0; j < 4; j++)
#pragma unroll
            for (int q = 0; q < 4; q++) acc[i][j][q] = 0.0f;

    int a_row_lane = lane & 15;
    int a_hi8      = lane >> 4;
    int b_row_lane = (lane & 7) + ((lane & 16) ? 8 : 0);
    int b_hi8      = (lane >> 3) & 1;

    load_stage(0, 0); CP_COMMIT();

    for (int kb = 0; kb < GNKB; kb++) {
        if (kb + 1 < GNKB) { load_stage((kb + 1) & 1, kb + 1); CP_COMMIT(); CP_WAIT(1); }
        else CP_WAIT(0);
        __syncthreads();

        uint32_t sb  = sbase + (kb & 1) * GSTG;
        uint32_t sAh = sb, sAl = sb + GBUF, sBh = sb + 2 * GBUF, sBl = sb + 3 * GBUF;

#pragma unroll
        for (int ks = 0; ks < 2; ks++) {
            uint32_t aH[4][4], aL[4][4], bH[4][2], bL[4][2];
#pragma unroll
            for (int mt = 0; mt < 4; mt++) {
                int row = wm * 64 + mt * 16 + a_row_lane;
                int ch  = ks * 2 + a_hi8;
                uint32_t off = (uint32_t)(row * GST + ch * 8) * 2;
                ldsm4(aH[mt], sAh + off);
                ldsm4(aL[mt], sAl + off);
            }
#pragma unroll
            for (int nt2 = 0; nt2 < 2; nt2++) {
                int row = wn * 32 + nt2 * 16 + b_row_lane;
                int ch  = ks * 2 + b_hi8;
                uint32_t off = (uint32_t)(row * GST + ch * 8) * 2;
                uint32_t r4[4];
                ldsm4(r4, sBh + off);
                bH[nt2*2][0] = r4[0]; bH[nt2*2][1] = r4[1];
                bH[nt2*2+1][0] = r4[2]; bH[nt2*2+1][1] = r4[3];
                ldsm4(r4, sBl + off);
                bL[nt2*2][0] = r4[0]; bL[nt2*2][1] = r4[1];
                bL[nt2*2+1][0] = r4[2]; bL[nt2*2+1][1] = r4[3];
            }
#pragma unroll
            for (int mt = 0; mt < 4; mt++)
#pragma unroll
                for (int nt = 0; nt < 4; nt++)
                    mma16816(acc[mt][nt], aH[mt], bH[nt]);
#pragma unroll
            for (int mt = 0; mt < 4; mt++)
#pragma unroll
                for (int nt = 0; nt < 4; nt++)
                    mma16816(acc[mt][nt], aH[mt], bL[nt]);
#pragma unroll
            for (int mt = 0; mt < 4; mt++)
#pragma unroll
                for (int nt = 0; nt < 4; nt++)
                    mma16816(acc[mt][nt], aL[mt], bH[nt]);
        }
        __syncthreads();
    }

#pragma unroll
    for (int mt = 0; mt < 4; mt++) {
        int row = m0 + wm * 64 + mt * 16 + (lane >> 2);
#pragma unroll
        for (int nt = 0; nt < 4; nt++) {
            int col = n0 + wn * 32 + nt * 8 + (lane & 3) * 2;
            float2 v0 = make_float2(acc[mt][nt][0], acc[mt][nt][1]);
            float2 v1 = make_float2(acc[mt][nt][2], acc[mt][nt][3]);
            if (OUTMODE == 1) {
                v0.x += bias[col]; v0.y += bias[col + 1];
                v1.x += bias[col]; v1.y += bias[col + 1];
            }
            if (OUTMODE == 2) {
                *(uint32_t*)&Ch[(size_t)row * DIM + col] = pack_trunc(v0.x, v0.y);
                *(uint32_t*)&Cl[(size_t)row * DIM + col] = pack_resid(v0.x, v0.y);
                *(uint32_t*)&Ch[(size_t)(row + 8) * DIM + col] = pack_trunc(v1.x, v1.y);
                *(uint32_t*)&Cl[(size_t)(row + 8) * DIM + col] = pack_resid(v1.x, v1.y);
            } else {
                *(float2*)&C[(size_t)row * DIM + col] = v0;
                *(float2*)&C[(size_t)(row + 8) * DIM + col] = v1;
            }
        }
    }
}

// ---------------------------------------------------------------------------
// RoPE over full DIM, fused with bf16 hi/lo split of rotated q,k
// ---------------------------------------------------------------------------
__global__ void rope_split_kernel(const float* __restrict__ q, const float* __restrict__ k,
                                  unsigned short* __restrict__ qh, unsigned short* __restrict__ ql,
                                  unsigned short* __restrict__ kh, unsigned short* __restrict__ kl)
{
    const int HALF = DIM / 2;
    int idx = blockIdx.x * blockDim.x + threadIdx.x;
    if (idx >= MTOT * HALF) return;
    int p = idx % HALF;
    int row = idx / HALF;
    int s = row % SEQ;

    float ex = (float)(2 * p) / (float)DIM;
    float freq = powf(10000.0f, -ex);
    float ang = (float)s * freq;
    float sn, cs;
    sincosf(ang, &sn, &cs);

    size_t base = (size_t)row * DIM + 2 * p;
    float q0 = q[base], q1 = q[base + 1];
    float k0 = k[base], k1 = k[base + 1];
    float qr0 = q0 * cs - q1 * sn, qr1 = q0 * sn + q1 * cs;
    float kr0 = k0 * cs - k1 * sn, kr1 = k0 * sn + k1 * cs;

    *(uint32_t*)&qh[base] = pack_trunc(qr0, qr1);
    *(uint32_t*)&ql[base] = pack_resid(qr0, qr1);
    *(uint32_t*)&kh[base] = pack_trunc(kr0, kr1);
    *(uint32_t*)&kl[base] = pack_resid(kr0, kr1);
}

// ---------------------------------------------------------------------------
// Tensor-core flash attention, bf16 split, 128 q-rows/CTA, key tiles of 128.
// 8 warps, each owns 16 q rows. Output written bf16-split for O-proj.
// ---------------------------------------------------------------------------
#define FTS 72
#define FROWB 144
#define FTILE (128*FROWB)           // 18432 B
#define FQOFF 0
#define FKV0 (2*FTILE)
#define FSTG (4*FTILE)              // Kh,Kl,Vh,Vl
#define FLASH_SMEM (2*FTILE + 2*FSTG)   // 184320 B
#define NKT (SEQ/128)               // 8

__global__ void __launch_bounds__(256, 1)
flash_mma(const unsigned short* __restrict__ Qh, const unsigned short* __restrict__ Ql,
          const unsigned short* __restrict__ Kh, const unsigned short* __restrict__ Kl,
          const unsigned short* __restrict__ Vh, const unsigned short* __restrict__ Vl,
          unsigned short* __restrict__ Oh, unsigned short* __restrict__ Ol)
{
    extern __shared__ char smf[];
    uint32_t sbase = smem_u32(smf);
    int tid = threadIdx.x;
    int wid = tid >> 5, lane = tid & 31;
    int b = blockIdx.z, h = blockIdx.y;
    int q0 = blockIdx.x * 128;

    size_t qrow0 = (size_t)(b * SEQ + q0);
    size_t krow0 = (size_t)(b * SEQ);
    int hc = h * HD;

    // ---- Q load (once) ----
    {
#pragma unroll
        for (int i = 0; i < 4; i++) {
            int c = tid + i * 256;             // 1024 chunks
            int row = c >> 3, ch = c & 7;
            uint32_t so = sbase + FQOFF + row * FROWB + ch * 16;
            size_t go = (qrow0 + row) * DIM + hc + ch * 8;
            cp16(so, Qh + go);
            cp16(so + FTILE, Ql + go);
        }
        CP_COMMIT();
    }

    auto load_kv = [&](int t) {
        uint32_t sb = sbase + FKV0 + (t & 1) * FSTG;
        size_t rbase = (krow0 + (size_t)t * 128) * DIM + hc;
#pragma unroll
        for (int i = 0; i < 4; i++) {
            int c = tid + i * 256;
            int row = c >> 3, ch = c & 7;
            uint32_t so = sb + row * FROWB + ch * 16;
            size_t go = rbase + (size_t)row * DIM + ch * 8;
            cp16(so,             Kh + go);
            cp16(so + FTILE,     Kl + go);
            cp16(so + 2 * FTILE, Vh + go);
            cp16(so + 3 * FTILE, Vl + go);
        }
        CP_COMMIT();
    };

    load_kv(0);

    // per-thread state
    float out[8][4];
#pragma unroll
    for (int i = 0; i < 8; i++)
#pragma unroll
        for (int j = 0; j < 4; j++) out[i][j] = 0.0f;
    float m2[2] = {-1e30f, -1e30f};
    float lsum[2] = {0.0f, 0.0f};

    uint32_t aQh[4][4], aQl[4][4];
    const float C2 = 0.18033688f;   // 0.125 * log2(e)

    int a_row_lane = lane & 15;
    int a_hi8      = lane >> 4;
    int b_row_lane = (lane & 7) + ((lane & 16) ? 8 : 0);
    int b_hi8      = (lane >> 3) & 1;
    // trans-ldsm lane addressing for V
    int v_krel = (lane & 7) + ((lane & 8) ? 8 : 0);
    int v_chi  = (lane & 16) ? 8 : 0;

    for (int t = 0; t < NKT; t++) {
        if (t + 1 < NKT) { load_kv(t + 1); CP_WAIT(1); }
        else CP_WAIT(0);
        __syncthreads();

        if (t == 0) {
            // load Q frags once (Q smem now valid)
#pragma unroll
            for (int kk = 0; kk < 4; kk++) {
                int row = wid * 16 + a_row_lane;
                uint32_t off = sbase + FQOFF + row * FROWB + (kk * 16 + a_hi8 * 8) * 2;
                ldsm4(aQh[kk], off);
                ldsm4(aQl[kk], off + FTILE);
            }
        }

        uint32_t sK = sbase + FKV0 + (t & 1) * FSTG;
        uint32_t sKl = sK + FTILE, sV = sK + 2 * FTILE, sVl = sK + 3 * FTILE;

        // ---- QK^T: acc[16 n8-tiles][4] ----
        float acc[16][4];
#pragma unroll
        for (int i = 0; i < 16; i++)
#pragma unroll
            for (int j = 0; j < 4; j++) acc[i][j] = 0.0f;

#pragma unroll
        for (int kk = 0; kk < 4; kk++) {
#pragma unroll
            for (int ntp = 0; ntp < 8; ntp++) {
                int row = ntp * 16 + b_row_lane;
                uint32_t off = row * FROWB + (kk * 16 + b_hi8 * 8) * 2;
                uint32_t bh4[4], bl4[4];
                ldsm4(bh4, sK + off);
                ldsm4(bl4, sKl + off);
                mma16816(acc[2*ntp],   aQh[kk], bh4);
                mma16816(acc[2*ntp+1], aQh[kk], bh4 + 2);
                mma16816(acc[2*ntp],   aQh[kk], bl4);
                mma16816(acc[2*ntp+1], aQh[kk], bl4 + 2);
                mma16816(acc[2*ntp],   aQl[kk], bh4);
                mma16816(acc[2*ntp+1], aQl[kk], bh4 + 2);
            }
        }

        // ---- online softmax (rows: r0 = lane>>2, r1 = r0+8) ----
        float lm0 = -1e30f, lm1 = -1e30f;
#pragma unroll
        for (int nt = 0; nt < 16; nt++) {
            lm0 = fmaxf(lm0, fmaxf(acc[nt][0], acc[nt][1]));
            lm1 = fmaxf(lm1, fmaxf(acc[nt][2], acc[nt][3]));
        }
        lm0 = fmaxf(lm0, __shfl_xor_sync(0xffffffffu, lm0, 1));
        lm0 = fmaxf(lm0, __shfl_xor_sync(0xffffffffu, lm0, 2));
        lm1 = fmaxf(lm1, __shfl_xor_sync(0xffffffffu, lm1, 1));
        lm1 = fmaxf(lm1, __shfl_xor_sync(0xffffffffu, lm1, 2));
        float nm0 = fmaxf(m2[0], lm0 * C2);
        float nm1 = fmaxf(m2[1], lm1 * C2);
        float sc0 = exp2f(m2[0] - nm0);
        float sc1 = exp2f(m2[1] - nm1);
        m2[0] = nm0; m2[1] = nm1;

        float rs0 = 0.0f, rs1 = 0.0f;
#pragma unroll
        for (int nt = 0; nt < 16; nt++) {
            acc[nt][0] = exp2f(acc[nt][0] * C2 - nm0);
            acc[nt][1] = exp2f(acc[nt][1] * C2 - nm0);
            acc[nt][2] = exp2f(acc[nt][2] * C2 - nm1);
            acc[nt][3] = exp2f(acc[nt][3] * C2 - nm1);
            rs0 += acc[nt][0] + acc[nt][1];
            rs1 += acc[nt][2] + acc[nt][3];
        }
        rs0 += __shfl_xor_sync(0xffffffffu, rs0, 1);
        rs0 += __shfl_xor_sync(0xffffffffu, rs0, 2);
        rs1 += __shfl_xor_sync(0xffffffffu, rs1, 1);
        rs1 += __shfl_xor_sync(0xffffffffu, rs1, 2);
        lsum[0] = lsum[0] * sc0 + rs0;
        lsum[1] = lsum[1] * sc1 + rs1;

#pragma unroll
        for (int i = 0; i < 8; i++) {
            out[i][0] *= sc0; out[i][1] *= sc0;
            out[i][2] *= sc1; out[i][3] *= sc1;
        }

        // ---- P · V ----
#pragma unroll
        for (int s = 0; s < 8; s++) {
            uint32_t aPh[4], aPl[4];
            aPh[0] = pack_trunc(acc[2*s][0],   acc[2*s][1]);
            aPh[1] = pack_trunc(acc[2*s][2],   acc[2*s][3]);
            aPh[2] = pack_trunc(acc[2*s+1][0], acc[2*s+1][1]);
            aPh[3] = pack_trunc(acc[2*s+1][2], acc[2*s+1][3]);
            aPl[0] = pack_resid(acc[2*s][0],   acc[2*s][1]);
            aPl[1] = pack_resid(acc[2*s][2],   acc[2*s][3]);
            aPl[2] = pack_resid(acc[2*s+1][0], acc[2*s+1][1]);
            aPl[3] = pack_resid(acc[2*s+1][2], acc[2*s+1][3]);

#pragma unroll
            for (int g = 0; g < 4; g++) {
                uint32_t off = (s * 16 + v_krel) * FROWB + (g * 16 + v_chi) * 2;
                uint32_t vh4[4], vl4[4];
                ldsm4t(vh4, sV + off);
                ldsm4t(vl4, sVl + off);
                mma16816(out[2*g],   aPh, vh4);
                mma16816(out[2*g+1], aPh, vh4 + 2);
                mma16816(out[2*g],   aPh, vl4);
                mma16816(out[2*g+1], aPh, vl4 + 2);
                mma16816(out[2*g],   aPl, vh4);
                mma16816(out[2*g+1], aPl, vh4 + 2);
            }
        }
        __syncthreads();
    }

    // ---- epilogue: normalize + split write ----
    float inv0 = 1.0f / lsum[0];
    float inv1 = 1.0f / lsum[1];
    size_t gr0 = (qrow0 + wid * 16 + (lane >> 2)) * DIM;
    size_t gr1 = gr0 + 8 * DIM;
#pragma unroll
    for (int nt = 0; nt < 8; nt++) {
        int col = hc + nt * 8 + (lane & 3) * 2;
        float f0 = out[nt][0] * inv0, f1 = out[nt][1] * inv0;
        float f2 = out[nt][2] * inv1, f3 = out[nt][3] * inv1;
        *(uint32_t*)&Oh[gr0 + col] = pack_trunc(f0, f1);
        *(uint32_t*)&Ol[gr0 + col] = pack_resid(f0, f1);
        *(uint32_t*)&Oh[gr1 + col] = pack_trunc(f2, f3);
        *(uint32_t*)&Ol[gr1 + col] = pack_resid(f2, f3);
    }
}

// ---------------------------------------------------------------------------
// Launch
// ---------------------------------------------------------------------------
extern "C" void kernel_launch(void* const* d_in, const int* in_sizes, int n_in,
                              void* d_out, int out_size)
{
    const float* x  = (const float*)d_in[0];
    const float* Wq = (const float*)d_in[1];
    const float* Wk = (const float*)d_in[2];
    const float* Wv = (const float*)d_in[3];
    const float* Wo = (const float*)d_in[4];
    const float* bo = (const float*)d_in[5];
    float* out = (float*)d_out;

    float *gq, *gk;
    unsigned short *xh, *xl, *qh, *ql, *kh, *kl, *vh, *vl, *ah, *al;
    unsigned short *wqh, *wql, *wkh, *wkl, *wvh, *wvl, *woh, *wol;
    cudaGetSymbolAddress((void**)&gq, g_q);
    cudaGetSymbolAddress((void**)&gk, g_k);
    cudaGetSymbolAddress((void**)&xh, g_xh);
    cudaGetSymbolAddress((void**)&xl, g_xl);
    cudaGetSymbolAddress((void**)&qh, g_qh);
    cudaGetSymbolAddress((void**)&ql, g_ql);
    cudaGetSymbolAddress((void**)&kh, g_kh);
    cudaGetSymbolAddress((void**)&kl, g_kl);
    cudaGetSymbolAddress((void**)&vh, g_vh);
    cudaGetSymbolAddress((void**)&vl, g_vl);
    cudaGetSymbolAddress((void**)&ah, g_ah);
    cudaGetSymbolAddress((void**)&al, g_al);
    cudaGetSymbolAddress((void**)&wqh, g_wqh);
    cudaGetSymbolAddress((void**)&wql, g_wql);
    cudaGetSymbolAddress((void**)&wkh, g_wkh);
    cudaGetSymbolAddress((void**)&wkl, g_wkl);
    cudaGetSymbolAddress((void**)&wvh, g_wvh);
    cudaGetSymbolAddress((void**)&wvl, g_wvl);
    cudaGetSymbolAddress((void**)&woh, g_woh);
    cudaGetSymbolAddress((void**)&wol, g_wol);

    cudaFuncSetAttribute(gemm_hmma<0>, cudaFuncAttributeMaxDynamicSharedMemorySize, GEMM_SMEM);
    cudaFuncSetAttribute(gemm_hmma<1>, cudaFuncAttributeMaxDynamicSharedMemorySize, GEMM_SMEM);
    cudaFuncSetAttribute(gemm_hmma<2>, cudaFuncAttributeMaxDynamicSharedMemorySize, GEMM_SMEM);
    cudaFuncSetAttribute(flash_mma, cudaFuncAttributeMaxDynamicSharedMemorySize, FLASH_SMEM);

    int n4x = MTOT * DIM / 4;
    int n4w = DIM * DIM / 4;
    split_kernel<<<(n4x + 255) / 256, 256>>>(x, xh, xl, n4x);
    split_kernel<<<(n4w + 255) / 256, 256>>>(Wq, wqh, wql, n4w);
    split_kernel<<<(n4w + 255) / 256, 256>>>(Wk, wkh, wkl, n4w);
    split_kernel<<<(n4w + 255) / 256, 256>>>(Wv, wvh, wvl, n4w);
    split_kernel<<<(n4w + 255) / 256, 256>>>(Wo, woh, wol, n4w);

    dim3 gg(DIM / GBN, MTOT / GBM);
    gemm_hmma<0><<<gg, 256, GEMM_SMEM>>>(xh, xl, wqh, wql, nullptr, gq, nullptr, nullptr);
    gemm_hmma<0><<<gg, 256, GEMM_SMEM>>>(xh, xl, wkh, wkl, nullptr, gk, nullptr, nullptr);
    gemm_hmma<2><<<gg, 256, GEMM_SMEM>>>(xh, xl, wvh, wvl, nullptr, nullptr, vh, vl);

    int pairs = MTOT * (DIM / 2);
    rope_split_kernel<<<(pairs + 255) / 256, 256>>>(gq, gk, qh, ql, kh, kl);

    flash_mma<<<dim3(SEQ / 128, NH, BSZ), 256, FLASH_SMEM>>>(qh, ql, kh, kl, vh, vl, ah, al);

    gemm_hmma<1><<<gg, 256, GEMM_SMEM>>>(ah, al, woh, wol, bo, out, nullptr, nullptr);
}

// round 6
// speedup vs baseline: 2.7845x; 1.1005x over previous
#include <cuda_runtime.h>
#include <cuda_bf16.h>
#include <math.h>
#include <stdint.h>

#define DIM 1024
#define BSZ 4
#define SEQ 1024
#define NH 16
#define HD 64
#define MTOT (BSZ*SEQ)

// ---------------------------------------------------------------------------
// Scratch (device globals, no allocations)
// ---------------------------------------------------------------------------
__device__ float g_q[MTOT*DIM];
__device__ float g_k[MTOT*DIM];
__device__ unsigned short g_xh[MTOT*DIM], g_xl[MTOT*DIM];
__device__ unsigned short g_qh[MTOT*DIM], g_ql[MTOT*DIM];
__device__ unsigned short g_kh[MTOT*DIM], g_kl[MTOT*DIM];
__device__ unsigned short g_vh[MTOT*DIM], g_vl[MTOT*DIM];
__device__ unsigned short g_ah[MTOT*DIM], g_al[MTOT*DIM];
__device__ unsigned short g_wqh[DIM*DIM], g_wql[DIM*DIM];
__device__ unsigned short g_wkh[DIM*DIM], g_wkl[DIM*DIM];
__device__ unsigned short g_wvh[DIM*DIM], g_wvl[DIM*DIM];
__device__ unsigned short g_woh[DIM*DIM], g_wol[DIM*DIM];

// ---------------------------------------------------------------------------
// Helpers (base-target PTX only)
// ---------------------------------------------------------------------------
__device__ __forceinline__ uint32_t smem_u32(const void* p) {
    uint32_t a;
    asm("{ .reg .u64 t; cvta.to.shared.u64 t, %1; cvt.u32.u64 %0, t; }" : "=r"(a) : "l"(p));
    return a;
}

__device__ __forceinline__ void ldsm4(uint32_t* r, uint32_t addr) {
    asm volatile("ldmatrix.sync.aligned.m8n8.x4.shared.b16 {%0,%1,%2,%3}, [%4];"
                 : "=r"(r[0]), "=r"(r[1]), "=r"(r[2]), "=r"(r[3]) : "r"(addr));
}
__device__ __forceinline__ void ldsm4t(uint32_t* r, uint32_t addr) {
    asm volatile("ldmatrix.sync.aligned.m8n8.x4.trans.shared.b16 {%0,%1,%2,%3}, [%4];"
                 : "=r"(r[0]), "=r"(r[1]), "=r"(r[2]), "=r"(r[3]) : "r"(addr));
}

__device__ __forceinline__ void mma16816(float* c, const uint32_t* a, const uint32_t* b) {
    asm volatile(
        "mma.sync.aligned.m16n8k16.row.col.f32.bf16.bf16.f32 "
        "{%0,%1,%2,%3}, {%4,%5,%6,%7}, {%8,%9}, {%0,%1,%2,%3};\n"
        : "+f"(c[0]), "+f"(c[1]), "+f"(c[2]), "+f"(c[3])
        : "r"(a[0]), "r"(a[1]), "r"(a[2]), "r"(a[3]), "r"(b[0]), "r"(b[1]));
}

__device__ __forceinline__ void cp16(uint32_t saddr, const void* g) {
    asm volatile("cp.async.cg.shared.global [%0], [%1], 16;" :: "r"(saddr), "l"(g));
}
#define CP_COMMIT() asm volatile("cp.async.commit_group;" ::: "memory")
#define CP_WAIT(n)  asm volatile("cp.async.wait_group %0;" :: "n"(n) : "memory")

__device__ __forceinline__ uint32_t pack_trunc(float c0, float c1) {
    return (__float_as_uint(c1) & 0xFFFF0000u) | (__float_as_uint(c0) >> 16);
}
__device__ __forceinline__ uint32_t pack_resid(float c0, float c1) {
    float r0 = c0 - __uint_as_float(__float_as_uint(c0) & 0xFFFF0000u);
    float r1 = c1 - __uint_as_float(__float_as_uint(c1) & 0xFFFF0000u);
    uint32_t b0 = (uint32_t)__bfloat16_as_ushort(__float2bfloat16(r0));
    uint32_t b1 = (uint32_t)__bfloat16_as_ushort(__float2bfloat16(r1));
    return b0 | (b1 << 16);
}

// ---------------------------------------------------------------------------
// Merged fp32 -> (bf16 hi, bf16 lo) split for x + 4 weights in ONE launch
// ---------------------------------------------------------------------------
#define N4X (MTOT*DIM/4)
#define N4W (DIM*DIM/4)

__global__ void split_all(const float* __restrict__ x,
                          const float* __restrict__ wq, const float* __restrict__ wk,
                          const float* __restrict__ wv, const float* __restrict__ wo,
                          unsigned short* __restrict__ xh, unsigned short* __restrict__ xl,
                          unsigned short* __restrict__ wqh, unsigned short* __restrict__ wql,
                          unsigned short* __restrict__ wkh, unsigned short* __restrict__ wkl,
                          unsigned short* __restrict__ wvh, unsigned short* __restrict__ wvl,
                          unsigned short* __restrict__ woh, unsigned short* __restrict__ wol)
{
    int i = blockIdx.x * blockDim.x + threadIdx.x;
    const float* src; unsigned short* hi; unsigned short* lo; int j;
    if (i < N4X)            { src = x;  hi = xh;  lo = xl;  j = i; }
    else if (i < N4X+N4W)   { src = wq; hi = wqh; lo = wql; j = i - N4X; }
    else if (i < N4X+2*N4W) { src = wk; hi = wkh; lo = wkl; j = i - N4X - N4W; }
    else if (i < N4X+3*N4W) { src = wv; hi = wvh; lo = wvl; j = i - N4X - 2*N4W; }
    else if (i < N4X+4*N4W) { src = wo; hi = woh; lo = wol; j = i - N4X - 3*N4W; }
    else return;

    float4 v = ((const float4*)src)[j];
    float vv[4] = {v.x, v.y, v.z, v.w};
    unsigned short h[4], l[4];
#pragma unroll
    for (int q = 0; q < 4; q++) {
        uint32_t b  = __float_as_uint(vv[q]);
        uint32_t hb = b & 0xFFFF0000u;
        h[q] = (unsigned short)(hb >> 16);
        l[q] = __bfloat16_as_ushort(__float2bfloat16(vv[q] - __uint_as_float(hb)));
    }
    ((uint2*)hi)[j] = make_uint2((uint32_t)h[0] | ((uint32_t)h[1] << 16),
                                 (uint32_t)h[2] | ((uint32_t)h[3] << 16));
    ((uint2*)lo)[j] = make_uint2((uint32_t)l[0] | ((uint32_t)l[1] << 16),
                                 (uint32_t)l[2] | ((uint32_t)l[3] << 16));
}

// ---------------------------------------------------------------------------
// HMMA GEMM: CTA tile 128x256, BK=32, 8 warps (2x4), warp tile 64x64.
// bf16-split 3-pass. OUTMODE: 0=fp32, 1=fp32+bias, 2=bf16split
// ---------------------------------------------------------------------------
#define GBM 128
#define GBN 256
#define GBK 32
#define GST 56                        // smem row stride (bf16 elems)
#define ABUF (128*GST*2)              // 14336 B
#define BBUF (256*GST*2)              // 28672 B
#define GSTG (2*ABUF + 2*BBUF)        // 86016 B
#define GEMM_SMEM (2*GSTG)            // 172032 B
#define GNKB (DIM/GBK)                // 32

template<int OUTMODE>
__global__ void __launch_bounds__(256, 1)
gemm_hmma(const unsigned short* __restrict__ Ah,
          const unsigned short* __restrict__ Al,
          const unsigned short* __restrict__ Bh,
          const unsigned short* __restrict__ Bl,
          const float* __restrict__ bias,
          float* __restrict__ C,
          unsigned short* __restrict__ Ch,
          unsigned short* __restrict__ Cl)
{
    extern __shared__ char smc[];
    uint32_t sbase = smem_u32(smc);
    int tid  = threadIdx.x;
    int wid  = tid >> 5, lane = tid & 31;
    int wm   = wid >> 2;               // 0..1  (64-row half)
    int wn   = wid & 3;                // 0..3  (64-col quarter)
    int m0   = blockIdx.y * GBM;
    int n0   = blockIdx.x * GBN;

    const unsigned short* gAh = Ah + (size_t)m0 * DIM;
    const unsigned short* gAl = Al + (size_t)m0 * DIM;
    const unsigned short* gBh = Bh + (size_t)n0 * DIM;
    const unsigned short* gBl = Bl + (size_t)n0 * DIM;

    auto load_stage = [&](int p, int kb) {
        uint32_t sb = sbase + p * GSTG;
        // A: 512 chunks of 16B, x2 matrices
#pragma unroll
        for (int r = 0; r < 2; r++) {
            int c = tid + 256 * r;
            int row = c >> 2, kc = c & 3;
            uint32_t so = (uint32_t)(row * GST + kc * 8) * 2;
            size_t go = (size_t)row * DIM + kb * GBK + kc * 8;
            cp16(sb + so,        gAh + go);
            cp16(sb + ABUF + so, gAl + go);
        }
        // B: 1024 chunks of 16B, x2 matrices
#pragma unroll
        for (int r = 0; r < 4; r++) {
            int c = tid + 256 * r;
            int row = c >> 2, kc = c & 3;
            uint32_t so = (uint32_t)(row * GST + kc * 8) * 2;
            size_t go = (size_t)row * DIM + kb * GBK + kc * 8;
            cp16(sb + 2 * ABUF + so,        gBh + go);
            cp16(sb + 2 * ABUF + BBUF + so, gBl + go);
        }
    };

    float acc[4][8][4];
#pragma unroll
    for (int i = 0; i < 4; i++)
#pragma unroll
        for (int j = 0; j < 8; j++)
#pragma unroll
            for (int q = 0; q < 4; q++) acc[i][j][q] = 0.0f;

    int a_row_lane = lane & 15;
    int a_hi8      = lane >> 4;
    int b_row_lane = (lane & 7) + ((lane & 16) ? 8 : 0);
    int b_hi8      = (lane >> 3) & 1;

    load_stage(0, 0); CP_COMMIT();

    for (int kb = 0; kb < GNKB; kb++) {
        if (kb + 1 < GNKB) { load_stage((kb + 1) & 1, kb + 1); CP_COMMIT(); CP_WAIT(1); }
        else CP_WAIT(0);
        __syncthreads();

        uint32_t sb  = sbase + (kb & 1) * GSTG;
        uint32_t sAh = sb, sAl = sb + ABUF;
        uint32_t sBh = sb + 2 * ABUF, sBl = sb + 2 * ABUF + BBUF;

#pragma unroll
        for (int ks = 0; ks < 2; ks++) {
            uint32_t aH[4][4], aL[4][4];
#pragma unroll
            for (int mt = 0; mt < 4; mt++) {
                int row = wm * 64 + mt * 16 + a_row_lane;
                uint32_t off = (uint32_t)(row * GST + (ks * 2 + a_hi8) * 8) * 2;
                ldsm4(aH[mt], sAh + off);
                ldsm4(aL[mt], sAl + off);
            }
#pragma unroll
            for (int ng = 0; ng < 4; ng++) {
                int row = wn * 64 + ng * 16 + b_row_lane;
                uint32_t off = (uint32_t)(row * GST + (ks * 2 + b_hi8) * 8) * 2;
                uint32_t bh4[4], bl4[4];
                ldsm4(bh4, sBh + off);
                ldsm4(bl4, sBl + off);
#pragma unroll
                for (int mt = 0; mt < 4; mt++) {
                    mma16816(acc[mt][2*ng],   aH[mt], bh4);
                    mma16816(acc[mt][2*ng+1], aH[mt], bh4 + 2);
                    mma16816(acc[mt][2*ng],   aH[mt], bl4);
                    mma16816(acc[mt][2*ng+1], aH[mt], bl4 + 2);
                    mma16816(acc[mt][2*ng],   aL[mt], bh4);
                    mma16816(acc[mt][2*ng+1], aL[mt], bh4 + 2);
                }
            }
        }
        __syncthreads();
    }

#pragma unroll
    for (int mt = 0; mt < 4; mt++) {
        int row = m0 + wm * 64 + mt * 16 + (lane >> 2);
#pragma unroll
        for (int nt = 0; nt < 8; nt++) {
            int col = n0 + wn * 64 + nt * 8 + (lane & 3) * 2;
            float2 v0 = make_float2(acc[mt][nt][0], acc[mt][nt][1]);
            float2 v1 = make_float2(acc[mt][nt][2], acc[mt][nt][3]);
            if (OUTMODE == 1) {
                v0.x += bias[col]; v0.y += bias[col + 1];
                v1.x += bias[col]; v1.y += bias[col + 1];
            }
            if (OUTMODE == 2) {
                *(uint32_t*)&Ch[(size_t)row * DIM + col] = pack_trunc(v0.x, v0.y);
                *(uint32_t*)&Cl[(size_t)row * DIM + col] = pack_resid(v0.x, v0.y);
                *(uint32_t*)&Ch[(size_t)(row + 8) * DIM + col] = pack_trunc(v1.x, v1.y);
                *(uint32_t*)&Cl[(size_t)(row + 8) * DIM + col] = pack_resid(v1.x, v1.y);
            } else {
                *(float2*)&C[(size_t)row * DIM + col] = v0;
                *(float2*)&C[(size_t)(row + 8) * DIM + col] = v1;
            }
        }
    }
}

// ---------------------------------------------------------------------------
// RoPE over full DIM, fused with bf16 hi/lo split of rotated q,k
// ---------------------------------------------------------------------------
__global__ void rope_split_kernel(const float* __restrict__ q, const float* __restrict__ k,
                                  unsigned short* __restrict__ qh, unsigned short* __restrict__ ql,
                                  unsigned short* __restrict__ kh, unsigned short* __restrict__ kl)
{
    const int HALF = DIM / 2;
    int idx = blockIdx.x * blockDim.x + threadIdx.x;
    if (idx >= MTOT * HALF) return;
    int p = idx % HALF;
    int row = idx / HALF;
    int s = row % SEQ;

    float ex = (float)(2 * p) / (float)DIM;
    float freq = powf(10000.0f, -ex);
    float ang = (float)s * freq;
    float sn, cs;
    sincosf(ang, &sn, &cs);

    size_t base = (size_t)row * DIM + 2 * p;
    float q0 = q[base], q1 = q[base + 1];
    float k0 = k[base], k1 = k[base + 1];
    float qr0 = q0 * cs - q1 * sn, qr1 = q0 * sn + q1 * cs;
    float kr0 = k0 * cs - k1 * sn, kr1 = k0 * sn + k1 * cs;

    *(uint32_t*)&qh[base] = pack_trunc(qr0, qr1);
    *(uint32_t*)&ql[base] = pack_resid(qr0, qr1);
    *(uint32_t*)&kh[base] = pack_trunc(kr0, kr1);
    *(uint32_t*)&kl[base] = pack_resid(kr0, kr1);
}

// ---------------------------------------------------------------------------
// Tensor-core flash attention, bf16 split, 128 q-rows/CTA, key tiles of 128.
// ---------------------------------------------------------------------------
#define FROWB 144
#define FTILE (128*FROWB)
#define FQOFF 0
#define FKV0 (2*FTILE)
#define FSTG (4*FTILE)
#define FLASH_SMEM (2*FTILE + 2*FSTG)
#define NKT (SEQ/128)

__global__ void __launch_bounds__(256, 1)
flash_mma(const unsigned short* __restrict__ Qh, const unsigned short* __restrict__ Ql,
          const unsigned short* __restrict__ Kh, const unsigned short* __restrict__ Kl,
          const unsigned short* __restrict__ Vh, const unsigned short* __restrict__ Vl,
          unsigned short* __restrict__ Oh, unsigned short* __restrict__ Ol)
{
    extern __shared__ char smf[];
    uint32_t sbase = smem_u32(smf);
    int tid = threadIdx.x;
    int wid = tid >> 5, lane = tid & 31;
    int b = blockIdx.z, h = blockIdx.y;
    int q0 = blockIdx.x * 128;

    size_t qrow0 = (size_t)(b * SEQ + q0);
    size_t krow0 = (size_t)(b * SEQ);
    int hc = h * HD;

    {
#pragma unroll
        for (int i = 0; i < 4; i++) {
            int c = tid + i * 256;
            int row = c >> 3, ch = c & 7;
            uint32_t so = sbase + FQOFF + row * FROWB + ch * 16;
            size_t go = (qrow0 + row) * DIM + hc + ch * 8;
            cp16(so, Qh + go);
            cp16(so + FTILE, Ql + go);
        }
        CP_COMMIT();
    }

    auto load_kv = [&](int t) {
        uint32_t sb = sbase + FKV0 + (t & 1) * FSTG;
        size_t rbase = (krow0 + (size_t)t * 128) * DIM + hc;
#pragma unroll
        for (int i = 0; i < 4; i++) {
            int c = tid + i * 256;
            int row = c >> 3, ch = c & 7;
            uint32_t so = sb + row * FROWB + ch * 16;
            size_t go = rbase + (size_t)row * DIM + ch * 8;
            cp16(so,             Kh + go);
            cp16(so + FTILE,     Kl + go);
            cp16(so + 2 * FTILE, Vh + go);
            cp16(so + 3 * FTILE, Vl + go);
        }
        CP_COMMIT();
    };

    load_kv(0);

    float out[8][4];
#pragma unroll
    for (int i = 0; i < 8; i++)
#pragma unroll
        for (int j = 0; j < 4; j++) out[i][j] = 0.0f;
    float m2[2] = {-1e30f, -1e30f};
    float lsum[2] = {0.0f, 0.0f};

    uint32_t aQh[4][4], aQl[4][4];
    const float C2 = 0.18033688f;

    int a_row_lane = lane & 15;
    int a_hi8      = lane >> 4;
    int b_row_lane = (lane & 7) + ((lane & 16) ? 8 : 0);
    int b_hi8      = (lane >> 3) & 1;
    int v_krel = (lane & 7) + ((lane & 8) ? 8 : 0);
    int v_chi  = (lane & 16) ? 8 : 0;

    for (int t = 0; t < NKT; t++) {
        if (t + 1 < NKT) { load_kv(t + 1); CP_WAIT(1); }
        else CP_WAIT(0);
        __syncthreads();

        if (t == 0) {
#pragma unroll
            for (int kk = 0; kk < 4; kk++) {
                int row = wid * 16 + a_row_lane;
                uint32_t off = sbase + FQOFF + row * FROWB + (kk * 16 + a_hi8 * 8) * 2;
                ldsm4(aQh[kk], off);
                ldsm4(aQl[kk], off + FTILE);
            }
        }

        uint32_t sK = sbase + FKV0 + (t & 1) * FSTG;
        uint32_t sKl = sK + FTILE, sV = sK + 2 * FTILE, sVl = sK + 3 * FTILE;

        float acc[16][4];
#pragma unroll
        for (int i = 0; i < 16; i++)
#pragma unroll
            for (int j = 0; j < 4; j++) acc[i][j] = 0.0f;

#pragma unroll
        for (int kk = 0; kk < 4; kk++) {
#pragma unroll
            for (int ntp = 0; ntp < 8; ntp++) {
                int row = ntp * 16 + b_row_lane;
                uint32_t off = row * FROWB + (kk * 16 + b_hi8 * 8) * 2;
                uint32_t bh4[4], bl4[4];
                ldsm4(bh4, sK + off);
                ldsm4(bl4, sKl + off);
                mma16816(acc[2*ntp],   aQh[kk], bh4);
                mma16816(acc[2*ntp+1], aQh[kk], bh4 + 2);
                mma16816(acc[2*ntp],   aQh[kk], bl4);
                mma16816(acc[2*ntp+1], aQh[kk], bl4 + 2);
                mma16816(acc[2*ntp],   aQl[kk], bh4);
                mma16816(acc[2*ntp+1], aQl[kk], bh4 + 2);
            }
        }

        float lm0 = -1e30f, lm1 = -1e30f;
#pragma unroll
        for (int nt = 0; nt < 16; nt++) {
            lm0 = fmaxf(lm0, fmaxf(acc[nt][0], acc[nt][1]));
            lm1 = fmaxf(lm1, fmaxf(acc[nt][2], acc[nt][3]));
        }
        lm0 = fmaxf(lm0, __shfl_xor_sync(0xffffffffu, lm0, 1));
        lm0 = fmaxf(lm0, __shfl_xor_sync(0xffffffffu, lm0, 2));
        lm1 = fmaxf(lm1, __shfl_xor_sync(0xffffffffu, lm1, 1));
        lm1 = fmaxf(lm1, __shfl_xor_sync(0xffffffffu, lm1, 2));
        float nm0 = fmaxf(m2[0], lm0 * C2);
        float nm1 = fmaxf(m2[1], lm1 * C2);
        float sc0 = exp2f(m2[0] - nm0);
        float sc1 = exp2f(m2[1] - nm1);
        m2[0] = nm0; m2[1] = nm1;

        float rs0 = 0.0f, rs1 = 0.0f;
#pragma unroll
        for (int nt = 0; nt < 16; nt++) {
            acc[nt][0] = exp2f(acc[nt][0] * C2 - nm0);
            acc[nt][1] = exp2f(acc[nt][1] * C2 - nm0);
            acc[nt][2] = exp2f(acc[nt][2] * C2 - nm1);
            acc[nt][3] = exp2f(acc[nt][3] * C2 - nm1);
            rs0 += acc[nt][0] + acc[nt][1];
            rs1 += acc[nt][2] + acc[nt][3];
        }
        rs0 += __shfl_xor_sync(0xffffffffu, rs0, 1);
        rs0 += __shfl_xor_sync(0xffffffffu, rs0, 2);
        rs1 += __shfl_xor_sync(0xffffffffu, rs1, 1);
        rs1 += __shfl_xor_sync(0xffffffffu, rs1, 2);
        lsum[0] = lsum[0] * sc0 + rs0;
        lsum[1] = lsum[1] * sc1 + rs1;

#pragma unroll
        for (int i = 0; i < 8; i++) {
            out[i][0] *= sc0; out[i][1] *= sc0;
            out[i][2] *= sc1; out[i][3] *= sc1;
        }

#pragma unroll
        for (int s = 0; s < 8; s++) {
            uint32_t aPh[4], aPl[4];
            aPh[0] = pack_trunc(acc[2*s][0],   acc[2*s][1]);
            aPh[1] = pack_trunc(acc[2*s][2],   acc[2*s][3]);
            aPh[2] = pack_trunc(acc[2*s+1][0], acc[2*s+1][1]);
            aPh[3] = pack_trunc(acc[2*s+1][2], acc[2*s+1][3]);
            aPl[0] = pack_resid(acc[2*s][0],   acc[2*s][1]);
            aPl[1] = pack_resid(acc[2*s][2],   acc[2*s][3]);
            aPl[2] = pack_resid(acc[2*s+1][0], acc[2*s+1][1]);
            aPl[3] = pack_resid(acc[2*s+1][2], acc[2*s+1][3]);

#pragma unroll
            for (int g = 0; g < 4; g++) {
                uint32_t off = (s * 16 + v_krel) * FROWB + (g * 16 + v_chi) * 2;
                uint32_t vh4[4], vl4[4];
                ldsm4t(vh4, sV + off);
                ldsm4t(vl4, sVl + off);
                mma16816(out[2*g],   aPh, vh4);
                mma16816(out[2*g+1], aPh, vh4 + 2);
                mma16816(out[2*g],   aPh, vl4);
                mma16816(out[2*g+1], aPh, vl4 + 2);
                mma16816(out[2*g],   aPl, vh4);
                mma16816(out[2*g+1], aPl, vh4 + 2);
            }
        }
        __syncthreads();
    }

    float inv0 = 1.0f / lsum[0];
    float inv1 = 1.0f / lsum[1];
    size_t gr0 = (qrow0 + wid * 16 + (lane >> 2)) * DIM;
    size_t gr1 = gr0 + 8 * DIM;
#pragma unroll
    for (int nt = 0; nt < 8; nt++) {
        int col = hc + nt * 8 + (lane & 3) * 2;
        float f0 = out[nt][0] * inv0, f1 = out[nt][1] * inv0;
        float f2 = out[nt][2] * inv1, f3 = out[nt][3] * inv1;
        *(uint32_t*)&Oh[gr0 + col] = pack_trunc(f0, f1);
        *(uint32_t*)&Ol[gr0 + col] = pack_resid(f0, f1);
        *(uint32_t*)&Oh[gr1 + col] = pack_trunc(f2, f3);
        *(uint32_t*)&Ol[gr1 + col] = pack_resid(f2, f3);
    }
}

// ---------------------------------------------------------------------------
// Launch
// ---------------------------------------------------------------------------
extern "C" void kernel_launch(void* const* d_in, const int* in_sizes, int n_in,
                              void* d_out, int out_size)
{
    const float* x  = (const float*)d_in[0];
    const float* Wq = (const float*)d_in[1];
    const float* Wk = (const float*)d_in[2];
    const float* Wv = (const float*)d_in[3];
    const float* Wo = (const float*)d_in[4];
    const float* bo = (const float*)d_in[5];
    float* out = (float*)d_out;

    float *gq, *gk;
    unsigned short *xh, *xl, *qh, *ql, *kh, *kl, *vh, *vl, *ah, *al;
    unsigned short *wqh, *wql, *wkh, *wkl, *wvh, *wvl, *woh, *wol;
    cudaGetSymbolAddress((void**)&gq, g_q);
    cudaGetSymbolAddress((void**)&gk, g_k);
    cudaGetSymbolAddress((void**)&xh, g_xh);
    cudaGetSymbolAddress((void**)&xl, g_xl);
    cudaGetSymbolAddress((void**)&qh, g_qh);
    cudaGetSymbolAddress((void**)&ql, g_ql);
    cudaGetSymbolAddress((void**)&kh, g_kh);
    cudaGetSymbolAddress((void**)&kl, g_kl);
    cudaGetSymbolAddress((void**)&vh, g_vh);
    cudaGetSymbolAddress((void**)&vl, g_vl);
    cudaGetSymbolAddress((void**)&ah, g_ah);
    cudaGetSymbolAddress((void**)&al, g_al);
    cudaGetSymbolAddress((void**)&wqh, g_wqh);
    cudaGetSymbolAddress((void**)&wql, g_wql);
    cudaGetSymbolAddress((void**)&wkh, g_wkh);
    cudaGetSymbolAddress((void**)&wkl, g_wkl);
    cudaGetSymbolAddress((void**)&wvh, g_wvh);
    cudaGetSymbolAddress((void**)&wvl, g_wvl);
    cudaGetSymbolAddress((void**)&woh, g_woh);
    cudaGetSymbolAddress((void**)&wol, g_wol);

    cudaFuncSetAttribute(gemm_hmma<0>, cudaFuncAttributeMaxDynamicSharedMemorySize, GEMM_SMEM);
    cudaFuncSetAttribute(gemm_hmma<1>, cudaFuncAttributeMaxDynamicSharedMemorySize, GEMM_SMEM);
    cudaFuncSetAttribute(gemm_hmma<2>, cudaFuncAttributeMaxDynamicSharedMemorySize, GEMM_SMEM);
    cudaFuncSetAttribute(flash_mma, cudaFuncAttributeMaxDynamicSharedMemorySize, FLASH_SMEM);

    int total4 = N4X + 4 * N4W;
    split_all<<<(total4 + 255) / 256, 256>>>(x, Wq, Wk, Wv, Wo,
                                             xh, xl, wqh, wql, wkh, wkl,
                                             wvh, wvl, woh, wol);

    dim3 gg(DIM / GBN, MTOT / GBM);   // (4, 32) = 128 CTAs
    gemm_hmma<0><<<gg, 256, GEMM_SMEM>>>(xh, xl, wqh, wql, nullptr, gq, nullptr, nullptr);
    gemm_hmma<0><<<gg, 256, GEMM_SMEM>>>(xh, xl, wkh, wkl, nullptr, gk, nullptr, nullptr);
    gemm_hmma<2><<<gg, 256, GEMM_SMEM>>>(xh, xl, wvh, wvl, nullptr, nullptr, vh, vl);

    int pairs = MTOT * (DIM / 2);
    rope_split_kernel<<<(pairs + 255) / 256, 256>>>(gq, gk, qh, ql, kh, kl);

    flash_mma<<<dim3(SEQ / 128, NH, BSZ), 256, FLASH_SMEM>>>(qh, ql, kh, kl, vh, vl, ah, al);

    gemm_hmma<1><<<gg, 256, GEMM_SMEM>>>(ah, al, woh, wol, bo, out, nullptr, nullptr);
}